// round 3
// baseline (speedup 1.0000x reference)
#include <cuda_runtime.h>
#include <math.h>

#define Bq 4
#define Nq 4096
#define Hq 8
#define Dq 64
#define Mq 64
#define SEG 32
#define NPB (Nq/SEG)      // 128 rows per pass1 block
#define BH  (Bq*Hq)       // 32

typedef unsigned long long u64;

// Scratch (written fully every launch; no zeroing needed)
__device__ float g_KVp[SEG*BH*Dq*Mq];   // partial KV   [seg][bh][d][m]
__device__ float g_Ksp[SEG*BH*Dq];      // partial Ksum [seg][bh][d]
__device__ float g_KV[BH*Dq*Mq];        // reduced KV
__device__ float g_Ksum[BH*Dq];         // reduced Ksum

__device__ __forceinline__ float fmap(float x) {
    return x > 0.0f ? x + 1.0f : __expf(x);   // elu(x)+1
}

// ---- packed f32x2 helpers ----
__device__ __forceinline__ void ffma2(u64 &acc, u64 a, u64 b) {
    asm("fma.rn.f32x2 %0, %1, %2, %0;" : "+l"(acc) : "l"(a), "l"(b));
}
__device__ __forceinline__ void fadd2(u64 &acc, u64 a) {
    asm("add.rn.f32x2 %0, %1, %0;" : "+l"(acc) : "l"(a));
}
__device__ __forceinline__ float2 unpack2(u64 v) {
    float2 f; asm("mov.b64 {%0, %1}, %2;" : "=f"(f.x), "=f"(f.y) : "l"(v)); return f;
}

// ============ pass1: KV_partial[seg] = fmap(K)^T V over seg's rows ============
// grid (SEG, H, B), block 128. Each block: NPB=128 rows in 2 chunks of 64.
__global__ void __launch_bounds__(128) pass1_kernel(const float* __restrict__ Kp,
                                                    const float* __restrict__ Vp) {
    __shared__ float Ksh[64][64];     // fmapped K tile [row][d]
    __shared__ float Vdup[64][128];   // duplicated V  [row][2m]

    const int b = blockIdx.z, h = blockIdx.y, seg = blockIdx.x;
    const int bh = b * Hq + h;
    const int tid = threadIdx.x;
    const int d0 = (tid & 7) * 4;     // owns d: {d0..d0+3} U {d0+32..d0+35}
    const int m0 = (tid >> 3) * 4;    // owns m: m0..m0+3

    u64 acc[4][4];                    // [mi][dpair]: 0,1 -> d0,d0+2 ; 2,3 -> +32
    #pragma unroll
    for (int i = 0; i < 4; i++)
        #pragma unroll
        for (int j = 0; j < 4; j++) acc[i][j] = 0ull;
    u64 ks[4] = {0ull, 0ull, 0ull, 0ull};

    for (int c = 0; c < 2; c++) {
        const int n0 = seg * NPB + c * 64;
        __syncthreads();
        #pragma unroll
        for (int i = tid; i < 64 * 16; i += 128) {
            const int row = i >> 4, c4 = i & 15;
            const size_t base = ((size_t)(b * Nq + n0 + row) * Hq + h);
            float4 k4 = *(const float4*)(Kp + base * Dq + c4 * 4);
            k4.x = fmap(k4.x); k4.y = fmap(k4.y);
            k4.z = fmap(k4.z); k4.w = fmap(k4.w);
            *(float4*)&Ksh[row][c4 * 4] = k4;
            float4 v4 = *(const float4*)(Vp + base * Mq + c4 * 4);
            float4 lo = make_float4(v4.x, v4.x, v4.y, v4.y);
            float4 hi = make_float4(v4.z, v4.z, v4.w, v4.w);
            *(float4*)&Vdup[row][c4 * 8]     = lo;
            *(float4*)&Vdup[row][c4 * 8 + 4] = hi;
        }
        __syncthreads();

        #pragma unroll 4
        for (int n = 0; n < 64; n++) {
            const ulonglong2 kA = *(const ulonglong2*)&Ksh[n][d0];
            const ulonglong2 kB = *(const ulonglong2*)&Ksh[n][d0 + 32];
            const u64 v0 = *(const u64*)&Vdup[n][(m0 + 0) * 2];
            const u64 v1 = *(const u64*)&Vdup[n][(m0 + 1) * 2];
            const u64 v2 = *(const u64*)&Vdup[n][(m0 + 2) * 2];
            const u64 v3 = *(const u64*)&Vdup[n][(m0 + 3) * 2];
            ffma2(acc[0][0], v0, kA.x); ffma2(acc[0][1], v0, kA.y);
            ffma2(acc[0][2], v0, kB.x); ffma2(acc[0][3], v0, kB.y);
            ffma2(acc[1][0], v1, kA.x); ffma2(acc[1][1], v1, kA.y);
            ffma2(acc[1][2], v1, kB.x); ffma2(acc[1][3], v1, kB.y);
            ffma2(acc[2][0], v2, kA.x); ffma2(acc[2][1], v2, kA.y);
            ffma2(acc[2][2], v2, kB.x); ffma2(acc[2][3], v2, kB.y);
            ffma2(acc[3][0], v3, kA.x); ffma2(acc[3][1], v3, kA.y);
            ffma2(acc[3][2], v3, kB.x); ffma2(acc[3][3], v3, kB.y);
            if (tid < 8) {
                fadd2(ks[0], kA.x); fadd2(ks[1], kA.y);
                fadd2(ks[2], kB.x); fadd2(ks[3], kB.y);
            }
        }
    }

    // flush partials (no atomics: this block exclusively owns [seg][bh])
    float* kv = g_KVp + ((size_t)seg * BH + bh) * Dq * Mq;
    #pragma unroll
    for (int dp = 0; dp < 4; dp++) {
        const int dbase = (dp < 2) ? (d0 + dp * 2) : (d0 + 32 + (dp - 2) * 2);
        float2 p0 = unpack2(acc[0][dp]);
        float2 p1 = unpack2(acc[1][dp]);
        float2 p2 = unpack2(acc[2][dp]);
        float2 p3 = unpack2(acc[3][dp]);
        *(float4*)(kv + (size_t)dbase * Mq + m0) =
            make_float4(p0.x, p1.x, p2.x, p3.x);
        *(float4*)(kv + (size_t)(dbase + 1) * Mq + m0) =
            make_float4(p0.y, p1.y, p2.y, p3.y);
    }
    if (tid < 8) {
        float* kss = g_Ksp + ((size_t)seg * BH + bh) * Dq;
        float2 s0 = unpack2(ks[0]), s1 = unpack2(ks[1]);
        float2 s2 = unpack2(ks[2]), s3 = unpack2(ks[3]);
        *(float4*)(kss + d0)      = make_float4(s0.x, s0.y, s1.x, s1.y);
        *(float4*)(kss + d0 + 32) = make_float4(s2.x, s2.y, s3.x, s3.y);
    }
}

// ============ reduce: sum SEG partials ============
__global__ void __launch_bounds__(256) reduce_kernel() {
    const int i = blockIdx.x * 256 + threadIdx.x;
    if (i < BH * Dq * Mq) {
        float s = 0.0f;
        #pragma unroll
        for (int sg = 0; sg < SEG; sg++) s += g_KVp[(size_t)sg * BH * Dq * Mq + i];
        g_KV[i] = s;
    }
    if (i < BH * Dq) {
        float s = 0.0f;
        #pragma unroll
        for (int sg = 0; sg < SEG; sg++) s += g_Ksp[sg * BH * Dq + i];
        g_Ksum[i] = s;
    }
}

// ============ pass2: out = Z * fmap(Q) @ KV ============
// grid (64, H, B), block 128. Dynamic smem: Z(64) Kss(64) KV(64x64) Qdup(64x128)
__global__ void __launch_bounds__(128) pass2_kernel(const float* __restrict__ Qp,
                                                    float* __restrict__ Op) {
    extern __shared__ float sm[];
    float* Zsh = sm;                                   // 64
    float* Kss = sm + 64;                              // 64
    float (*KVsh)[64]  = (float(*)[64])(sm + 128);     // [d][m]
    float (*Qdup)[128] = (float(*)[128])(sm + 128 + Dq * Mq); // [n][2d]

    const int b = blockIdx.z, h = blockIdx.y;
    const int bh = b * Hq + h;
    const int n0 = blockIdx.x * 64;
    const int tid = threadIdx.x;

    const float4* kvg = (const float4*)(g_KV + (size_t)bh * Dq * Mq);
    #pragma unroll
    for (int i = tid; i < Dq * Mq / 4; i += 128)
        ((float4*)KVsh)[i] = kvg[i];
    if (tid < 64) Kss[tid] = g_Ksum[bh * Dq + tid];

    #pragma unroll
    for (int i = tid; i < 64 * 16; i += 128) {
        const int row = i >> 4, c4 = i & 15;
        float4 q4 = *(const float4*)(Qp + ((size_t)(b * Nq + n0 + row) * Hq + h) * Dq + c4 * 4);
        q4.x = fmap(q4.x); q4.y = fmap(q4.y);
        q4.z = fmap(q4.z); q4.w = fmap(q4.w);
        *(float4*)&Qdup[row][c4 * 8]     = make_float4(q4.x, q4.x, q4.y, q4.y);
        *(float4*)&Qdup[row][c4 * 8 + 4] = make_float4(q4.z, q4.z, q4.w, q4.w);
    }
    __syncthreads();

    if (tid < 64) {
        float s = 0.0f;
        #pragma unroll
        for (int d = 0; d < Dq; d++) s += Qdup[tid][2 * d] * Kss[d];
        Zsh[tid] = 1.0f / (s + 1e-6f);
    }
    __syncthreads();

    const int m0 = (tid & 7) * 4;     // owns m: {m0..m0+3} U {m0+32..m0+35}
    const int nb = (tid >> 3) * 4;    // owns n rows nb..nb+3
    u64 acc[4][4];                    // [ni][mpair]: 0,1 -> m0,m0+2 ; 2,3 -> +32
    #pragma unroll
    for (int i = 0; i < 4; i++)
        #pragma unroll
        for (int j = 0; j < 4; j++) acc[i][j] = 0ull;

    #pragma unroll 4
    for (int d = 0; d < Dq; d++) {
        const ulonglong2 kA = *(const ulonglong2*)&KVsh[d][m0];
        const ulonglong2 kB = *(const ulonglong2*)&KVsh[d][m0 + 32];
        const u64 q0 = *(const u64*)&Qdup[nb + 0][2 * d];
        const u64 q1 = *(const u64*)&Qdup[nb + 1][2 * d];
        const u64 q2 = *(const u64*)&Qdup[nb + 2][2 * d];
        const u64 q3 = *(const u64*)&Qdup[nb + 3][2 * d];
        ffma2(acc[0][0], q0, kA.x); ffma2(acc[0][1], q0, kA.y);
        ffma2(acc[0][2], q0, kB.x); ffma2(acc[0][3], q0, kB.y);
        ffma2(acc[1][0], q1, kA.x); ffma2(acc[1][1], q1, kA.y);
        ffma2(acc[1][2], q1, kB.x); ffma2(acc[1][3], q1, kB.y);
        ffma2(acc[2][0], q2, kA.x); ffma2(acc[2][1], q2, kA.y);
        ffma2(acc[2][2], q2, kB.x); ffma2(acc[2][3], q2, kB.y);
        ffma2(acc[3][0], q3, kA.x); ffma2(acc[3][1], q3, kA.y);
        ffma2(acc[3][2], q3, kB.x); ffma2(acc[3][3], q3, kB.y);
    }

    #pragma unroll
    for (int ni = 0; ni < 4; ni++) {
        const float z = Zsh[nb + ni];
        float2 p0 = unpack2(acc[ni][0]);
        float2 p1 = unpack2(acc[ni][1]);
        float2 p2 = unpack2(acc[ni][2]);
        float2 p3 = unpack2(acc[ni][3]);
        float* op = Op + ((size_t)(b * Nq + n0 + nb + ni) * Hq + h) * Mq;
        *(float4*)(op + m0)      = make_float4(p0.x * z, p0.y * z, p1.x * z, p1.y * z);
        *(float4*)(op + m0 + 32) = make_float4(p2.x * z, p2.y * z, p3.x * z, p3.y * z);
    }
}

extern "C" void kernel_launch(void* const* d_in, const int* in_sizes, int n_in,
                              void* d_out, int out_size) {
    const float* Q = (const float*)d_in[0];
    const float* K = (const float*)d_in[1];
    const float* V = (const float*)d_in[2];
    float* out = (float*)d_out;

    const int p2_smem = (64 + 64 + Dq * Mq + 64 * 128) * sizeof(float); // 49664 B
    cudaFuncSetAttribute(pass2_kernel, cudaFuncAttributeMaxDynamicSharedMemorySize, p2_smem);

    pass1_kernel<<<dim3(SEG, Hq, Bq), 128>>>(K, V);
    reduce_kernel<<<512, 256>>>();
    pass2_kernel<<<dim3(64, Hq, Bq), 128, p2_smem>>>(Q, out);
}

// round 4
// speedup vs baseline: 2.3344x; 2.3344x over previous
#include <cuda_runtime.h>
#include <math.h>

#define Bq 4
#define Nq 4096
#define Hq 8
#define Dq 64
#define Mq 64
#define SEG 16
#define BH  (Bq*Hq)
#define P   68          // smem row pitch in floats

// Scratch (fully written each launch)
__device__ float g_KVp[SEG*BH*Dq*Mq];   // partial KV [seg][bh][d][m]
__device__ float g_Ksp[SEG*BH*Dq];      // partial Ksum
__device__ float g_KV[BH*Dq*Mq];
__device__ float g_Ksum[BH*Dq];

__device__ __forceinline__ float fmap(float x) {
    return x > 0.0f ? x + 1.0f : __expf(x);   // elu(x)+1
}
__device__ __forceinline__ float tf32r(float x) {
    float r; asm("cvt.rna.tf32.f32 %0, %1;" : "=f"(r) : "f"(x)); return r;
}
__device__ __forceinline__ void mma_tf32(float4& d,
                                         unsigned a0, unsigned a1, unsigned a2, unsigned a3,
                                         unsigned b0, unsigned b1) {
    asm volatile(
        "mma.sync.aligned.m16n8k8.row.col.f32.tf32.tf32.f32 "
        "{%0,%1,%2,%3}, {%4,%5,%6,%7}, {%8,%9}, {%0,%1,%2,%3};"
        : "+f"(d.x), "+f"(d.y), "+f"(d.z), "+f"(d.w)
        : "r"(a0), "r"(a1), "r"(a2), "r"(a3), "r"(b0), "r"(b1));
}
__device__ __forceinline__ unsigned fau(float x) { return __float_as_uint(x); }

// ============ pass1: KV_partial[seg][bh] = fmap(K)^T V over this seg's 256 rows ============
// grid (SEG, H, B), block 256 (8 warps). D tile = 64(d) x 64(m).
// Warp w: Mtile(d-strip) = w%4 (rows 16*(w%4)..+15), ntiles (m) = 4*(w/4)..+3.
__global__ void __launch_bounds__(256) pass1_kernel(const float* __restrict__ Kp,
                                                    const float* __restrict__ Vp) {
    __shared__ float Ksm[64][P];   // fmapped+tf32 K tile, [n][d]
    __shared__ float Vsm[64][P];   // tf32 V tile,         [n][m]

    const int b = blockIdx.z, h = blockIdx.y, seg = blockIdx.x;
    const int bh = b * Hq + h;
    const int tid = threadIdx.x;
    const int w = tid >> 5, lane = tid & 31;
    const int gid = lane >> 2, tig = lane & 3;
    const int mt = w & 3;
    const int jt0 = (w >> 2) * 4;

    float4 acc[4];
    #pragma unroll
    for (int j = 0; j < 4; j++) acc[j] = make_float4(0.f, 0.f, 0.f, 0.f);
    float ksum = 0.0f;  // valid for tid < 64 (d = tid)

    for (int c = 0; c < 4; c++) {
        const int n0 = seg * 256 + c * 64;
        __syncthreads();
        // stage 64 rows: 1024 float4 jobs, coalesced; fmap+cvt on the fly
        #pragma unroll
        for (int it = 0; it < 4; it++) {
            const int idx = it * 256 + tid;
            const int n = idx >> 4, c4 = idx & 15;
            const size_t base = ((size_t)(b * Nq + n0 + n) * Hq + h);
            float4 k4 = *(const float4*)(Kp + base * Dq + c4 * 4);
            k4.x = tf32r(fmap(k4.x)); k4.y = tf32r(fmap(k4.y));
            k4.z = tf32r(fmap(k4.z)); k4.w = tf32r(fmap(k4.w));
            *(float4*)&Ksm[n][c4 * 4] = k4;
            float4 v4 = *(const float4*)(Vp + base * Mq + c4 * 4);
            v4.x = tf32r(v4.x); v4.y = tf32r(v4.y);
            v4.z = tf32r(v4.z); v4.w = tf32r(v4.w);
            *(float4*)&Vsm[n][c4 * 4] = v4;
        }
        __syncthreads();

        // Ksum partial for this chunk (threads 0..63, d = tid)
        if (tid < 64) {
            float s = 0.0f;
            #pragma unroll 8
            for (int n = 0; n < 64; n++) s += Ksm[n][tid];
            ksum += s;
        }

        // MMA mainloop: contraction over the 64 staged rows (8 k-steps of 8)
        #pragma unroll
        for (int ks = 0; ks < 8; ks++) {
            const int k0 = ks * 8;
            // A = K'^T: A[d][n] gathered from Ksm[n][d] (index swap, no transpose)
            const unsigned a0 = fau(Ksm[k0 + tig    ][16 * mt + gid    ]);
            const unsigned a1 = fau(Ksm[k0 + tig    ][16 * mt + gid + 8]);
            const unsigned a2 = fau(Ksm[k0 + tig + 4][16 * mt + gid    ]);
            const unsigned a3 = fau(Ksm[k0 + tig + 4][16 * mt + gid + 8]);
            #pragma unroll
            for (int j = 0; j < 4; j++) {
                const unsigned b0 = fau(Vsm[k0 + tig    ][(jt0 + j) * 8 + gid]);
                const unsigned b1 = fau(Vsm[k0 + tig + 4][(jt0 + j) * 8 + gid]);
                mma_tf32(acc[j], a0, a1, a2, a3, b0, b1);
            }
        }
    }

    // epilogue: write partial KV (block exclusively owns [seg][bh])
    float* kv = g_KVp + ((size_t)seg * BH + bh) * Dq * Mq;
    const int d = 16 * mt + gid;
    #pragma unroll
    for (int j = 0; j < 4; j++) {
        const int m = (jt0 + j) * 8 + 2 * tig;
        *(float2*)(kv + (size_t)d * Mq + m)       = make_float2(acc[j].x, acc[j].y);
        *(float2*)(kv + (size_t)(d + 8) * Mq + m) = make_float2(acc[j].z, acc[j].w);
    }
    if (tid < 64) g_Ksp[((size_t)seg * BH + bh) * Dq + tid] = ksum;
}

// ============ reduce: sum SEG partials ============
__global__ void __launch_bounds__(256) reduce_kernel() {
    const int i = blockIdx.x * 256 + threadIdx.x;
    if (i < BH * Dq * Mq) {
        float s = 0.0f;
        #pragma unroll
        for (int sg = 0; sg < SEG; sg++) s += g_KVp[(size_t)sg * BH * Dq * Mq + i];
        g_KV[i] = s;
    }
    if (i < BH * Dq) {
        float s = 0.0f;
        #pragma unroll
        for (int sg = 0; sg < SEG; sg++) s += g_Ksp[sg * BH * Dq + i];
        g_Ksum[i] = s;
    }
}

// ============ pass2: out = Z * fmap(Q) @ KV ============
// grid (32, H, B), block 256 (8 warps). Tile: 128 n-rows x 64 m, contraction d=64.
// Warp w: Mtile(n-strip) = w (rows 16w..16w+15), all 8 ntiles.
__global__ void __launch_bounds__(256) pass2_kernel(const float* __restrict__ Qp,
                                                    float* __restrict__ Op) {
    extern __shared__ float sm2[];
    float (*Qsm)[P]  = (float(*)[P])sm2;                 // [128][P]
    float (*KVsm)[P] = (float(*)[P])(sm2 + 128 * P);     // [64][P]
    float* Zs  = sm2 + 192 * P;                           // [128]
    float* Kss = Zs + 128;                                // [64]

    const int b = blockIdx.z, h = blockIdx.y;
    const int bh = b * Hq + h;
    const int n0 = blockIdx.x * 128;
    const int tid = threadIdx.x;
    const int w = tid >> 5, lane = tid & 31;
    const int gid = lane >> 2, tig = lane & 3;

    // stage KV (tf32-rounded for the MMA B operand)
    #pragma unroll
    for (int it = 0; it < 4; it++) {
        const int idx = it * 256 + tid;
        const int d = idx >> 4, c4 = idx & 15;
        float4 t = *(const float4*)(g_KV + (size_t)bh * Dq * Mq + d * Mq + c4 * 4);
        t.x = tf32r(t.x); t.y = tf32r(t.y); t.z = tf32r(t.z); t.w = tf32r(t.w);
        *(float4*)&KVsm[d][c4 * 4] = t;
    }
    if (tid < 64) Kss[tid] = g_Ksum[bh * Dq + tid];

    // stage Q' (fmap + tf32)
    #pragma unroll
    for (int it = 0; it < 8; it++) {
        const int idx = it * 256 + tid;
        const int n = idx >> 4, c4 = idx & 15;
        float4 q4 = *(const float4*)(Qp + ((size_t)(b * Nq + n0 + n) * Hq + h) * Dq + c4 * 4);
        q4.x = tf32r(fmap(q4.x)); q4.y = tf32r(fmap(q4.y));
        q4.z = tf32r(fmap(q4.z)); q4.w = tf32r(fmap(q4.w));
        *(float4*)&Qsm[n][c4 * 4] = q4;
    }
    __syncthreads();

    // Z per row
    if (tid < 128) {
        float s = 0.0f;
        #pragma unroll 8
        for (int d = 0; d < Dq; d++) s += Qsm[tid][d] * Kss[d];
        Zs[tid] = 1.0f / (s + 1e-6f);
    }
    __syncthreads();

    float4 acc[8];
    #pragma unroll
    for (int j = 0; j < 8; j++) acc[j] = make_float4(0.f, 0.f, 0.f, 0.f);

    #pragma unroll
    for (int ks = 0; ks < 8; ks++) {
        const int k0 = ks * 8;
        const unsigned a0 = fau(Qsm[16 * w + gid    ][k0 + tig    ]);
        const unsigned a1 = fau(Qsm[16 * w + gid + 8][k0 + tig    ]);
        const unsigned a2 = fau(Qsm[16 * w + gid    ][k0 + tig + 4]);
        const unsigned a3 = fau(Qsm[16 * w + gid + 8][k0 + tig + 4]);
        #pragma unroll
        for (int j = 0; j < 8; j++) {
            const unsigned b0 = fau(KVsm[k0 + tig    ][j * 8 + gid]);
            const unsigned b1 = fau(KVsm[k0 + tig + 4][j * 8 + gid]);
            mma_tf32(acc[j], a0, a1, a2, a3, b0, b1);
        }
    }

    // epilogue: scale by Z, store
    const int row = 16 * w + gid;
    const float z0 = Zs[row], z1 = Zs[row + 8];
    float* op0 = Op + ((size_t)(b * Nq + n0 + row) * Hq + h) * Mq;
    float* op1 = op0 + (size_t)8 * Hq * Mq;
    #pragma unroll
    for (int j = 0; j < 8; j++) {
        const int m = j * 8 + 2 * tig;
        *(float2*)(op0 + m) = make_float2(acc[j].x * z0, acc[j].y * z0);
        *(float2*)(op1 + m) = make_float2(acc[j].z * z1, acc[j].w * z1);
    }
}

extern "C" void kernel_launch(void* const* d_in, const int* in_sizes, int n_in,
                              void* d_out, int out_size) {
    const float* Q = (const float*)d_in[0];
    const float* K = (const float*)d_in[1];
    const float* V = (const float*)d_in[2];
    float* out = (float*)d_out;

    const int p2_smem = (192 * P + 128 + 64) * sizeof(float);  // ~53 KB
    static int attr_set = 0;
    cudaFuncSetAttribute(pass2_kernel, cudaFuncAttributeMaxDynamicSharedMemorySize, p2_smem);
    (void)attr_set;

    pass1_kernel<<<dim3(SEG, Hq, Bq), 256>>>(K, V);
    reduce_kernel<<<512, 256>>>();
    pass2_kernel<<<dim3(32, Hq, Bq), 256, p2_smem>>>(Q, out);
}